// round 1
// baseline (speedup 1.0000x reference)
#include <cuda_runtime.h>

// ---------------------------------------------------------------------------
// TimeAggNet fused pipeline, fp32 with packed f32x2 FMA (2 samples per thread)
//   stage12: conv1(1->32,K10,s8,p1)+relu+maxpool(5,5)+relu  then
//            conv2(32->64,K3,s3)+relu+maxpool(3,3,p1)+relu  -> g_h2
//   stage3 : conv3(64->128,K4 over len4) == GEMM [BN,256]x[256,128]+relu -> g_h3
//   head   : feat[256,16384] @ wl^T + bl -> softmax -> out[256,3]
// ---------------------------------------------------------------------------

#define BS   256
#define NN   128
#define BN   (BS*NN)      // 32768 samples
#define TLEN 1216
#define C1   32
#define P1L  30
#define C2   64
#define L2C  10
#define C3   128
#define K3   256          // C2 * 4

typedef unsigned long long ull;

// packed-weight scratch (duplicated {w,w} for f32x2 broadcast)
__device__ float2 g_w1d[C1*10];
__device__ float2 g_b1d[C1];
__device__ float2 g_w2td[96*C2];   // [ci*3+k][co], dup-packed
__device__ float2 g_b2d[C2];
// activations scratch
__device__ float2 g_h2[(BN/2)*K3]; // [pair q][j], lo=sample 2q, hi=sample 2q+1
__device__ float  g_h3[(size_t)BN*C3];

__device__ __forceinline__ ull pk2(float a, float b) {
    ull r; asm("mov.b64 %0,{%1,%2};" : "=l"(r) : "f"(a), "f"(b)); return r;
}
__device__ __forceinline__ float2 upk(ull v) {
    float a, b; asm("mov.b64 {%0,%1},%2;" : "=f"(a), "=f"(b) : "l"(v));
    return make_float2(a, b);
}
__device__ __forceinline__ ull ffma2(ull a, ull b, ull c) {
    ull d; asm("fma.rn.f32x2 %0,%1,%2,%3;" : "=l"(d) : "l"(a), "l"(b), "l"(c));
    return d;
}

// ---------------------------------------------------------------------------
__global__ void setup_pack(const float* __restrict__ w1, const float* __restrict__ b1,
                           const float* __restrict__ w2, const float* __restrict__ b2) {
    int t = blockIdx.x * blockDim.x + threadIdx.x;   // 24*256 = 6144 threads
    if (t < C1*10) { float v = w1[t]; g_w1d[t] = make_float2(v, v); }
    if (t < C1)    { float v = b1[t]; g_b1d[t] = make_float2(v, v); }
    if (t < C2)    { float v = b2[t]; g_b2d[t] = make_float2(v, v); }
    if (t < 96*C2) {                       // transpose w2 [co][ci*3+k] -> [j][co]
        int j = t >> 6, co = t & 63;
        float v = w2[co*96 + j];
        g_w2td[t] = make_float2(v, v);
    }
}

// ---------------------------------------------------------------------------
// stage12: one block per sample pair, 128 threads
__global__ __launch_bounds__(128) void stage12(const float* __restrict__ x) {
    __shared__ __align__(16) float2 xs[TLEN];        // 9728 B
    __shared__ __align__(16) float2 p1s[C1*P1L];     // 7680 B
    __shared__ __align__(16) float2 c2p[C2*L2C];     // 5120 B (partial)
    __shared__ __align__(16) float2 c2s[C2*L2C];     // 5120 B

    const int q   = blockIdx.x;
    const int tid = threadIdx.x;
    const float* xA = x + (size_t)(2*q) * TLEN;
    const float* xB = xA + TLEN;

    for (int i = tid; i < TLEN; i += 128)
        xs[i] = make_float2(xA[i], xB[i]);
    __syncthreads();

    // ---- stage 1: conv1 + relu + pool5 (relu(max(conv)+... ) == max then relu)
    {
        const int c = tid >> 2, g = tid & 3;         // 4 threads per channel
        ull w[10];
        #pragma unroll
        for (int k = 0; k < 10; k++) w[k] = *(const ull*)&g_w1d[c*10 + k];
        const float2 b1v = g_b1d[c];

        #pragma unroll
        for (int i = 0; i < 8; i++) {
            const int p = g + 4*i;
            if (p < P1L) {
                float mA, mB;
                if (p == 0) {
                    // boundary (left pad): scalar, guarded
                    mA = -1e30f; mB = -1e30f;
                    #pragma unroll
                    for (int j = 0; j < 5; j++) {
                        ull acc = 0ull;
                        #pragma unroll
                        for (int k = 0; k < 10; k++) {
                            int m = 8*j + k - 1;
                            if (m >= 0) acc = ffma2(*(const ull*)&xs[m], w[k], acc);
                        }
                        float2 s = upk(acc);
                        mA = fmaxf(mA, s.x); mB = fmaxf(mB, s.y);
                    }
                } else {
                    // rolling 12-reg window; window j covers xs[40p+8j-1 .. +8]
                    ull r[12];
                    {
                        const ulonglong2* bp = (const ulonglong2*)&xs[40*p - 2];
                        #pragma unroll
                        for (int z = 0; z < 6; z++) {
                            ulonglong2 v = bp[z]; r[2*z] = v.x; r[2*z+1] = v.y;
                        }
                    }
                    ull acc = 0ull;
                    #pragma unroll
                    for (int k = 0; k < 10; k++) acc = ffma2(r[k+1], w[k], acc);
                    { float2 s = upk(acc); mA = s.x; mB = s.y; }
                    #pragma unroll
                    for (int j = 1; j < 5; j++) {
                        #pragma unroll
                        for (int z = 0; z < 4; z++) r[z] = r[z+8];
                        const ulonglong2* bp2 =
                            (const ulonglong2*)&xs[40*p - 2 + 8*j + 4];
                        #pragma unroll
                        for (int z = 0; z < 4; z++) {
                            ulonglong2 v = bp2[z]; r[4+2*z] = v.x; r[5+2*z] = v.y;
                        }
                        acc = 0ull;
                        #pragma unroll
                        for (int k = 0; k < 10; k++) acc = ffma2(r[k+1], w[k], acc);
                        float2 s = upk(acc);
                        mA = fmaxf(mA, s.x); mB = fmaxf(mB, s.y);
                    }
                }
                p1s[c*P1L + p] = make_float2(fmaxf(mA + b1v.x, 0.f),
                                             fmaxf(mB + b1v.y, 0.f));
            }
        }
    }
    __syncthreads();

    // ---- stage 2: conv2 + relu (64 channels x 10 positions); ci split in halves
    {
        const int co = tid & 63, half = tid >> 6;
        ull acc[10];
        #pragma unroll
        for (int t2 = 0; t2 < 10; t2++) acc[t2] = 0ull;

        const int ci0 = half * 16;
        #pragma unroll 2
        for (int ci = ci0; ci < ci0 + 16; ci++) {
            ull wk[3];
            #pragma unroll
            for (int k = 0; k < 3; k++)
                wk[k] = *(const ull*)&g_w2td[(ci*3 + k)*64 + co];
            const ulonglong2* prow = (const ulonglong2*)&p1s[ci*P1L];  // 240B aligned
            #pragma unroll
            for (int r2 = 0; r2 < 15; r2++) {
                ulonglong2 v = prow[r2];
                const int q0 = 2*r2, q1 = 2*r2 + 1;       // positions 3t+k
                acc[q0/3] = ffma2(v.x, wk[q0 % 3], acc[q0/3]);
                acc[q1/3] = ffma2(v.y, wk[q1 % 3], acc[q1/3]);
            }
        }
        if (half == 1) {
            #pragma unroll
            for (int t2 = 0; t2 < 10; t2++)
                *(ull*)&c2p[co*10 + t2] = acc[t2];
        }
        __syncthreads();
        if (half == 0) {
            const float2 b2v = g_b2d[co];
            #pragma unroll
            for (int t2 = 0; t2 < 10; t2++) {
                float2 o = upk(acc[t2]);
                float2 pp = c2p[co*10 + t2];
                c2s[co*10 + t2] = make_float2(fmaxf(o.x + pp.x + b2v.x, 0.f),
                                              fmaxf(o.y + pp.y + b2v.y, 0.f));
            }
        }
        __syncthreads();

        // ---- pool2 (k3,s3,pad1) + write h2 (values already >= 0)
        #pragma unroll
        for (int e = 0; e < 2; e++) {
            const int id  = tid + e*128;          // 0..255
            const int co2 = id >> 2, u = id & 3;
            float2 m = make_float2(0.f, 0.f);
            #pragma unroll
            for (int dt = 0; dt < 3; dt++) {
                int tt = 3*u - 1 + dt;
                if (tt >= 0 && tt < 10) {
                    float2 v = c2s[co2*10 + tt];
                    m.x = fmaxf(m.x, v.x); m.y = fmaxf(m.y, v.y);
                }
            }
            g_h2[(size_t)q*K3 + co2*4 + u] = m;   // j = ci*4+u matches w3 row layout
        }
    }
}

// ---------------------------------------------------------------------------
// stage3: GEMM [BN,256] x w3^T[256,128] + bias + relu.
// Block tile: 32 pairs (64 samples) x 128 co. 256 threads, 8 warps.
// Thread tile: 4 co (stride 32) x 4 pairs, f32x2 accumulators.
__global__ __launch_bounds__(256) void stage3k(const float* __restrict__ w3,
                                               const float* __restrict__ b3) {
    __shared__ __align__(16) float  w3s[32*129];  // transposed, pitch 129
    __shared__ __align__(16) float2 h2s[32*32];

    const int q0  = blockIdx.x * 32;              // pair base
    const int tid = threadIdx.x;
    const int c0  = tid & 31;
    const int p0  = (tid >> 5) * 4;               // warp -> 4 pairs

    ull acc[16];
    #pragma unroll
    for (int i = 0; i < 16; i++) acc[i] = 0ull;

    for (int jc = 0; jc < 256; jc += 32) {
        __syncthreads();
        #pragma unroll
        for (int i = 0; i < 16; i++) {            // stage w3 chunk transposed
            int l = tid + i*256;                  // 0..4095
            int co = l >> 5, j = l & 31;
            w3s[j*129 + co] = w3[co*256 + jc + j];
        }
        #pragma unroll
        for (int i = 0; i < 4; i++) {             // stage h2 chunk
            int l = tid + i*256;                  // 0..1023
            int pr = l >> 5, j = l & 31;
            h2s[pr*32 + j] = g_h2[(size_t)(q0 + pr)*K3 + jc + j];
        }
        __syncthreads();

        #pragma unroll 4
        for (int j = 0; j < 32; j++) {
            ull wp[4], hv[4];
            #pragma unroll
            for (int m = 0; m < 4; m++) {
                float wv = w3s[j*129 + c0 + 32*m];
                wp[m] = pk2(wv, wv);
            }
            #pragma unroll
            for (int p = 0; p < 4; p++)
                hv[p] = *(const ull*)&h2s[(p0 + p)*32 + j];
            #pragma unroll
            for (int m = 0; m < 4; m++)
                #pragma unroll
                for (int p = 0; p < 4; p++)
                    acc[m*4 + p] = ffma2(hv[p], wp[m], acc[m*4 + p]);
        }
    }

    #pragma unroll
    for (int m = 0; m < 4; m++) {
        const int co = c0 + 32*m;
        const float bb = b3[co];
        #pragma unroll
        for (int p = 0; p < 4; p++) {
            float2 v = upk(acc[m*4 + p]);
            const int s = 2*(q0 + p0 + p);
            g_h3[(size_t)s*C3 + co]       = fmaxf(v.x + bb, 0.f);
            g_h3[(size_t)(s+1)*C3 + co]   = fmaxf(v.y + bb, 0.f);
        }
    }
}

// ---------------------------------------------------------------------------
// head: logits = feat @ wl^T + bl; softmax. One block per batch row.
__global__ __launch_bounds__(256) void head(const float* __restrict__ wl,
                                            const float* __restrict__ bl,
                                            float* __restrict__ out) {
    __shared__ float red[3][256];
    const int b = blockIdx.x, tid = threadIdx.x;
    const float4* f4  = (const float4*)(g_h3 + (size_t)b*16384);
    const float4* u0p = (const float4*)(wl);
    const float4* u1p = (const float4*)(wl + 16384);
    const float4* u2p = (const float4*)(wl + 32768);

    float a0 = 0.f, a1 = 0.f, a2 = 0.f;
    for (int i = tid; i < 4096; i += 256) {
        float4 f = f4[i], u0 = u0p[i], u1 = u1p[i], u2 = u2p[i];
        a0 += f.x*u0.x + f.y*u0.y + f.z*u0.z + f.w*u0.w;
        a1 += f.x*u1.x + f.y*u1.y + f.z*u1.z + f.w*u1.w;
        a2 += f.x*u2.x + f.y*u2.y + f.z*u2.z + f.w*u2.w;
    }
    red[0][tid] = a0; red[1][tid] = a1; red[2][tid] = a2;
    __syncthreads();
    for (int s = 128; s > 0; s >>= 1) {
        if (tid < s) {
            red[0][tid] += red[0][tid + s];
            red[1][tid] += red[1][tid + s];
            red[2][tid] += red[2][tid + s];
        }
        __syncthreads();
    }
    if (tid == 0) {
        float l0 = red[0][0] + bl[0];
        float l1 = red[1][0] + bl[1];
        float l2 = red[2][0] + bl[2];
        float mx = fmaxf(l0, fmaxf(l1, l2));
        float e0 = expf(l0 - mx), e1 = expf(l1 - mx), e2 = expf(l2 - mx);
        float inv = 1.f / (e0 + e1 + e2);
        out[b*3 + 0] = e0*inv;
        out[b*3 + 1] = e1*inv;
        out[b*3 + 2] = e2*inv;
    }
}

// ---------------------------------------------------------------------------
extern "C" void kernel_launch(void* const* d_in, const int* in_sizes, int n_in,
                              void* d_out, int out_size) {
    const float* x  = (const float*)d_in[0];
    const float* w1 = (const float*)d_in[1];
    const float* b1 = (const float*)d_in[2];
    const float* w2 = (const float*)d_in[3];
    const float* b2 = (const float*)d_in[4];
    const float* w3 = (const float*)d_in[5];
    const float* b3 = (const float*)d_in[6];
    const float* wl = (const float*)d_in[7];
    const float* bl = (const float*)d_in[8];
    float* out = (float*)d_out;

    setup_pack<<<24, 256>>>(w1, b1, w2, b2);
    stage12<<<BN/2, 128>>>(x);
    stage3k<<<BN/64, 256>>>(w3, b3);
    head<<<BS, 256>>>(wl, bl, out);
}

// round 2
// speedup vs baseline: 1.0112x; 1.0112x over previous
#include <cuda_runtime.h>

// ---------------------------------------------------------------------------
// TimeAggNet fused pipeline, fp32 with packed f32x2 FMA (2 samples per thread)
// ---------------------------------------------------------------------------

#define BS   256
#define NN   128
#define BN   (BS*NN)      // 32768 samples
#define TLEN 1216
#define C1   32
#define P1L  30
#define C2   64
#define L2C  10
#define C3   128
#define K3   256          // C2 * 4

typedef unsigned long long ull;

// packed-weight scratch (duplicated {w,w} for f32x2 broadcast)
__device__ __align__(16) float2 g_w1d[C1*10];
__device__ __align__(16) float2 g_b1d[C1];
__device__ __align__(16) float2 g_w2td[96*C2];   // [ci*3+k][co], dup-packed
__device__ __align__(16) float2 g_b2d[C2];
// activations scratch
__device__ __align__(16) float2 g_h2[(BN/2)*K3]; // [pair q][j]
__device__ __align__(16) float  g_h3[(size_t)BN*C3];
__device__ float  g_part[BS][8][3];

__device__ __forceinline__ ull pk2(float a, float b) {
    ull r; asm("mov.b64 %0,{%1,%2};" : "=l"(r) : "f"(a), "f"(b)); return r;
}
__device__ __forceinline__ float2 upk(ull v) {
    float a, b; asm("mov.b64 {%0,%1},%2;" : "=f"(a), "=f"(b) : "l"(v));
    return make_float2(a, b);
}
__device__ __forceinline__ ull ffma2(ull a, ull b, ull c) {
    ull d; asm("fma.rn.f32x2 %0,%1,%2,%3;" : "=l"(d) : "l"(a), "l"(b), "l"(c));
    return d;
}
__device__ __forceinline__ ull addx2(ull a, ull b) {
    ull d; asm("add.rn.f32x2 %0,%1,%2;" : "=l"(d) : "l"(a), "l"(b));
    return d;
}

// ---------------------------------------------------------------------------
__global__ void setup_pack(const float* __restrict__ w1, const float* __restrict__ b1,
                           const float* __restrict__ w2, const float* __restrict__ b2) {
    int t = blockIdx.x * blockDim.x + threadIdx.x;
    if (t < C1*10) { float v = w1[t]; g_w1d[t] = make_float2(v, v); }
    if (t < C1)    { float v = b1[t]; g_b1d[t] = make_float2(v, v); }
    if (t < C2)    { float v = b2[t]; g_b2d[t] = make_float2(v, v); }
    if (t < 96*C2) {                       // transpose w2 [co][ci*3+k] -> [j][co]
        int j = t >> 6, co = t & 63;
        float v = w2[co*96 + j];
        g_w2td[t] = make_float2(v, v);
    }
}

// ---------------------------------------------------------------------------
// stage12: one block per sample pair, 128 threads
__global__ __launch_bounds__(128) void stage12(const float* __restrict__ x) {
    // xs is dead after stage1; its space is reused as the stage2 reduction buf
    __shared__ __align__(16) union SU {
        float2 xs[1220];          // [0..1] = zero pad, [2+i] = x[i]; 9760 B
        ull    red[2][20][32];    // 10240 B
    } u;
    __shared__ __align__(16) float2 p1s[C1*P1L];     // 7680 B
    __shared__ __align__(16) float2 c2s[C2*L2C];     // 5120 B

    const int q   = blockIdx.x;
    const int tid = threadIdx.x;
    const float* xA = x + (size_t)(2*q) * TLEN;
    const float* xB = xA + TLEN;

    for (int i = tid; i < 1220; i += 128) {
        float a = 0.f, b = 0.f;
        int m = i - 2;
        if (m >= 0 && m < TLEN) { a = xA[m]; b = xB[m]; }
        u.xs[i] = make_float2(a, b);
    }
    __syncthreads();

    // ---- stage 1: conv1 + relu + pool5  (uniform path; left pad handled by zeros)
    {
        const int c = tid >> 2, g = tid & 3;         // 4 threads per channel
        ull w[10];
        #pragma unroll
        for (int k = 0; k < 10; k++) w[k] = *(const ull*)&g_w1d[c*10 + k];
        const float2 b1v = g_b1d[c];

        #pragma unroll
        for (int i = 0; i < 8; i++) {
            const int p = g + 4*i;
            if (p < P1L) {
                const int B = 40*p;                  // u.xs[B+z] holds x[B-2+z]
                ull r[12];
                {
                    const ulonglong2* bp = (const ulonglong2*)&u.xs[B];
                    #pragma unroll
                    for (int z = 0; z < 6; z++) {
                        ulonglong2 v = bp[z]; r[2*z] = v.x; r[2*z+1] = v.y;
                    }
                }
                float mA, mB;
                ull acc = 0ull;
                #pragma unroll
                for (int k = 0; k < 10; k++) acc = ffma2(r[k+1], w[k], acc);
                { float2 s = upk(acc); mA = s.x; mB = s.y; }
                #pragma unroll
                for (int j = 1; j < 5; j++) {
                    #pragma unroll
                    for (int z = 0; z < 4; z++) r[z] = r[z+8];
                    const ulonglong2* bp2 = (const ulonglong2*)&u.xs[B + 8*j + 4];
                    #pragma unroll
                    for (int z = 0; z < 4; z++) {
                        ulonglong2 v = bp2[z]; r[4+2*z] = v.x; r[5+2*z] = v.y;
                    }
                    acc = 0ull;
                    #pragma unroll
                    for (int k = 0; k < 10; k++) acc = ffma2(r[k+1], w[k], acc);
                    float2 s = upk(acc);
                    mA = fmaxf(mA, s.x); mB = fmaxf(mB, s.y);
                }
                p1s[c*P1L + p] = make_float2(fmaxf(mA + b1v.x, 0.f),
                                             fmaxf(mB + b1v.y, 0.f));
            }
        }
    }
    __syncthreads();

    // ---- stage 2: conv2 + relu. 2 co per thread, warp w owns ci in [8w, 8w+8)
    {
        const int lane = tid & 31;          // co pair {2*lane, 2*lane+1}
        const int w    = tid >> 5;          // ci group
        ull acc[20];                        // [e*10 + t]
        #pragma unroll
        for (int s = 0; s < 20; s++) acc[s] = 0ull;

        #pragma unroll 2
        for (int cc = 0; cc < 8; cc++) {
            const int ci = 8*w + cc;
            ull wk0[3], wk1[3];
            #pragma unroll
            for (int k = 0; k < 3; k++) {
                ulonglong2 wp = *(const ulonglong2*)&g_w2td[(ci*3 + k)*64 + 2*lane];
                wk0[k] = wp.x; wk1[k] = wp.y;
            }
            const ulonglong2* prow = (const ulonglong2*)&p1s[ci*P1L];
            #pragma unroll
            for (int r2 = 0; r2 < 15; r2++) {
                ulonglong2 v = prow[r2];
                const int m0 = 2*r2, m1 = 2*r2 + 1;     // m = 3t+k
                acc[m0/3]      = ffma2(v.x, wk0[m0%3], acc[m0/3]);
                acc[10 + m0/3] = ffma2(v.x, wk1[m0%3], acc[10 + m0/3]);
                acc[m1/3]      = ffma2(v.y, wk0[m1%3], acc[m1/3]);
                acc[10 + m1/3] = ffma2(v.y, wk1[m1%3], acc[10 + m1/3]);
            }
        }

        // reduce 4 warps -> warp 0 (conflict-free [slot][lane] layout)
        if (w >= 2) {
            #pragma unroll
            for (int s = 0; s < 20; s++) u.red[w-2][s][lane] = acc[s];
        }
        __syncthreads();
        if (w < 2) {
            #pragma unroll
            for (int s = 0; s < 20; s++) acc[s] = addx2(acc[s], u.red[w][s][lane]);
        }
        __syncthreads();
        if (w == 1) {
            #pragma unroll
            for (int s = 0; s < 20; s++) u.red[0][s][lane] = acc[s];
        }
        __syncthreads();
        if (w == 0) {
            const float b0 = g_b2d[2*lane].x, b1 = g_b2d[2*lane+1].x;
            #pragma unroll
            for (int t = 0; t < 10; t++) {
                float2 o0 = upk(addx2(acc[t],      u.red[0][t][lane]));
                float2 o1 = upk(addx2(acc[10 + t], u.red[0][10 + t][lane]));
                c2s[(2*lane)*10 + t]   = make_float2(fmaxf(o0.x + b0, 0.f),
                                                     fmaxf(o0.y + b0, 0.f));
                c2s[(2*lane+1)*10 + t] = make_float2(fmaxf(o1.x + b1, 0.f),
                                                     fmaxf(o1.y + b1, 0.f));
            }
        }
        __syncthreads();

        // ---- pool2 (k3,s3,pad1) + write h2 (values already >= 0)
        #pragma unroll
        for (int e = 0; e < 2; e++) {
            const int id  = tid + e*128;          // 0..255
            const int co2 = id >> 2, uu = id & 3;
            float2 m = make_float2(0.f, 0.f);
            #pragma unroll
            for (int dt = 0; dt < 3; dt++) {
                int tt = 3*uu - 1 + dt;
                if (tt >= 0 && tt < 10) {
                    float2 v = c2s[co2*10 + tt];
                    m.x = fmaxf(m.x, v.x); m.y = fmaxf(m.y, v.y);
                }
            }
            g_h2[(size_t)q*K3 + co2*4 + uu] = m;
        }
    }
}

// ---------------------------------------------------------------------------
// stage3: GEMM [BN,256] x w3^T[256,128] + bias + relu.
__global__ __launch_bounds__(256) void stage3k(const float* __restrict__ w3,
                                               const float* __restrict__ b3) {
    __shared__ __align__(16) float  w3s[32*129];
    __shared__ __align__(16) float2 h2s[32*32];

    const int q0  = blockIdx.x * 32;
    const int tid = threadIdx.x;
    const int c0  = tid & 31;
    const int p0  = (tid >> 5) * 4;

    ull acc[16];
    #pragma unroll
    for (int i = 0; i < 16; i++) acc[i] = 0ull;

    for (int jc = 0; jc < 256; jc += 32) {
        __syncthreads();
        #pragma unroll
        for (int i = 0; i < 16; i++) {
            int l = tid + i*256;
            int co = l >> 5, j = l & 31;
            w3s[j*129 + co] = w3[co*256 + jc + j];
        }
        #pragma unroll
        for (int i = 0; i < 4; i++) {
            int l = tid + i*256;
            int pr = l >> 5, j = l & 31;
            h2s[pr*32 + j] = g_h2[(size_t)(q0 + pr)*K3 + jc + j];
        }
        __syncthreads();

        #pragma unroll 4
        for (int j = 0; j < 32; j++) {
            ull wp[4], hv[4];
            #pragma unroll
            for (int m = 0; m < 4; m++) {
                float wv = w3s[j*129 + c0 + 32*m];
                wp[m] = pk2(wv, wv);
            }
            #pragma unroll
            for (int p = 0; p < 4; p++)
                hv[p] = *(const ull*)&h2s[(p0 + p)*32 + j];
            #pragma unroll
            for (int m = 0; m < 4; m++)
                #pragma unroll
                for (int p = 0; p < 4; p++)
                    acc[m*4 + p] = ffma2(hv[p], wp[m], acc[m*4 + p]);
        }
    }

    #pragma unroll
    for (int m = 0; m < 4; m++) {
        const int co = c0 + 32*m;
        const float bb = b3[co];
        #pragma unroll
        for (int p = 0; p < 4; p++) {
            float2 v = upk(acc[m*4 + p]);
            const int s = 2*(q0 + p0 + p);
            g_h3[(size_t)s*C3 + co]       = fmaxf(v.x + bb, 0.f);
            g_h3[(size_t)(s+1)*C3 + co]   = fmaxf(v.y + bb, 0.f);
        }
    }
}

// ---------------------------------------------------------------------------
// headA: partial dot-products; 8 slices per batch row
__global__ __launch_bounds__(256) void headA(const float* __restrict__ wl) {
    __shared__ float red[3][256];
    const int b = blockIdx.x >> 3, s = blockIdx.x & 7;
    const int tid = threadIdx.x;
    const float4* f4  = (const float4*)(g_h3 + (size_t)b*16384);
    const float4* u0p = (const float4*)(wl);
    const float4* u1p = (const float4*)(wl + 16384);
    const float4* u2p = (const float4*)(wl + 32768);

    float a0 = 0.f, a1 = 0.f, a2 = 0.f;
    #pragma unroll
    for (int it = 0; it < 2; it++) {
        int i = s*512 + tid + it*256;
        float4 f = f4[i], u0 = u0p[i], u1 = u1p[i], u2 = u2p[i];
        a0 += f.x*u0.x + f.y*u0.y + f.z*u0.z + f.w*u0.w;
        a1 += f.x*u1.x + f.y*u1.y + f.z*u1.z + f.w*u1.w;
        a2 += f.x*u2.x + f.y*u2.y + f.z*u2.z + f.w*u2.w;
    }
    red[0][tid] = a0; red[1][tid] = a1; red[2][tid] = a2;
    __syncthreads();
    for (int st = 128; st > 0; st >>= 1) {
        if (tid < st) {
            red[0][tid] += red[0][tid + st];
            red[1][tid] += red[1][tid + st];
            red[2][tid] += red[2][tid + st];
        }
        __syncthreads();
    }
    if (tid == 0) {
        g_part[b][s][0] = red[0][0];
        g_part[b][s][1] = red[1][0];
        g_part[b][s][2] = red[2][0];
    }
}

// headB: finish logits + softmax
__global__ void headB(const float* __restrict__ bl, float* __restrict__ out) {
    const int b = blockIdx.x;
    if (threadIdx.x == 0) {
        float l0 = bl[0], l1 = bl[1], l2 = bl[2];
        #pragma unroll
        for (int s = 0; s < 8; s++) {
            l0 += g_part[b][s][0];
            l1 += g_part[b][s][1];
            l2 += g_part[b][s][2];
        }
        float mx = fmaxf(l0, fmaxf(l1, l2));
        float e0 = expf(l0 - mx), e1 = expf(l1 - mx), e2 = expf(l2 - mx);
        float inv = 1.f / (e0 + e1 + e2);
        out[b*3 + 0] = e0*inv;
        out[b*3 + 1] = e1*inv;
        out[b*3 + 2] = e2*inv;
    }
}

// ---------------------------------------------------------------------------
extern "C" void kernel_launch(void* const* d_in, const int* in_sizes, int n_in,
                              void* d_out, int out_size) {
    const float* x  = (const float*)d_in[0];
    const float* w1 = (const float*)d_in[1];
    const float* b1 = (const float*)d_in[2];
    const float* w2 = (const float*)d_in[3];
    const float* b2 = (const float*)d_in[4];
    const float* w3 = (const float*)d_in[5];
    const float* b3 = (const float*)d_in[6];
    const float* wl = (const float*)d_in[7];
    const float* bl = (const float*)d_in[8];
    float* out = (float*)d_out;

    setup_pack<<<24, 256>>>(w1, b1, w2, b2);
    stage12<<<BN/2, 128>>>(x);
    stage3k<<<BN/64, 256>>>(w3, b3);
    headA<<<BS*8, 256>>>(wl);
    headB<<<BS, 32>>>(bl, out);
}